// round 16
// baseline (speedup 1.0000x reference)
#include <cuda_runtime.h>
#include <cuda_bf16.h>
#include <math.h>
#include <stdint.h>

#define N_TOK 4096
#define EMBED 1024
#define NHEAD 16
#define HDIM 64
#define FFN 4096
#define QKV3 3072

// ---------------- fp32 scratch ----------------------------------------------
__device__ alignas(16) float g_qkv[N_TOK * QKV3];
__device__ alignas(16) float g_attn[N_TOK * EMBED];
__device__ alignas(16) float g_res1[N_TOK * EMBED];
__device__ alignas(16) float g_h[N_TOK * EMBED];
__device__ alignas(16) float g_ffn[N_TOK * FFN];
// ---------------- split-bf16 A operands [M][3K] ------------------------------
__device__ alignas(16) __nv_bfloat16 g_featsS[(size_t)N_TOK * 3 * EMBED];
__device__ alignas(16) __nv_bfloat16 g_attnS[(size_t)N_TOK * 3 * EMBED];
__device__ alignas(16) __nv_bfloat16 g_hS[(size_t)N_TOK * 3 * EMBED];
__device__ alignas(16) __nv_bfloat16 g_ffnS[(size_t)N_TOK * 3 * FFN];
// ---------------- split-bf16 transposed weights [N][3K] ----------------------
__device__ alignas(16) __nv_bfloat16 g_wqkvT[(size_t)QKV3 * 3 * EMBED];
__device__ alignas(16) __nv_bfloat16 g_woT[(size_t)EMBED * 3 * EMBED];
__device__ alignas(16) __nv_bfloat16 g_w1T[(size_t)FFN * 3 * EMBED];
__device__ alignas(16) __nv_bfloat16 g_w2T[(size_t)EMBED * 3 * FFN];

// ---------------- split helpers ---------------------------------------------
// A' row: [ hi(0..K-1) | hi(0..K-1) | lo(0..K-1) ]
template <int LOGK>
__global__ void split_kernel(const float* __restrict__ src,
                             __nv_bfloat16* __restrict__ dst, int total) {
    int i = blockIdx.x * 256 + threadIdx.x;
    if (i >= total) return;
    const int K = 1 << LOGK;
    int r = i >> LOGK, k = i & (K - 1);
    float x = src[i];
    __nv_bfloat16 hi = __float2bfloat16(x);
    __nv_bfloat16 lo = __float2bfloat16(x - __bfloat162float(hi));
    size_t base = (size_t)r * (3 * K);
    dst[base + k] = hi;
    dst[base + K + k] = hi;
    dst[base + 2 * K + k] = lo;
}

// W [K][N] fp32 -> dst [N][3K] bf16 rows: [ hiW | loW | hiW ]
__global__ void transpose_split_kernel(const float* __restrict__ W,
                                       __nv_bfloat16* __restrict__ dst,
                                       int K, int N) {
    __shared__ float t[32][33];
    int k0 = blockIdx.y * 32, n0 = blockIdx.x * 32;
    int tx = threadIdx.x & 31, ty = threadIdx.x >> 5;  // 8 rows
#pragma unroll
    for (int j = 0; j < 4; j++) {
        int kk = ty + j * 8;
        t[kk][tx] = W[(size_t)(k0 + kk) * N + n0 + tx];
    }
    __syncthreads();
#pragma unroll
    for (int j = 0; j < 4; j++) {
        int n = ty + j * 8;
        int k = tx;
        float x = t[k][n];
        __nv_bfloat16 hi = __float2bfloat16(x);
        __nv_bfloat16 lo = __float2bfloat16(x - __bfloat162float(hi));
        size_t base = (size_t)(n0 + n) * (3 * K);
        dst[base + k0 + k] = hi;
        dst[base + K + k0 + k] = lo;
        dst[base + 2 * K + k0 + k] = hi;
    }
}

// ---------------- split-bf16 mma.sync GEMM ----------------------------------
// C[M][N] = A'(M,K2) . W'(N,K2)^T ; K2 = 3K. bf16 m16n8k16, fp32 accum.
// Block tile 128x256, chunk = 64 bf16 of K2 (= 32 packed words), 3 stages.
#define NSTAGE 3
#define BM 128
#define BN 256
#define BKW 32          // packed bf16x2 words per chunk (64 halves)
#define ASTW 36         // word stride: %32==4 -> bank(4g+t) conflict-free
#define BSTW 36
#define A_TILE_W (BM * ASTW)          // 4608 words
#define B_TILE_W (BN * BSTW)          // 9216 words
#define STAGE_W (A_TILE_W + B_TILE_W) // 13824 words = 55296 B
#define GEMM_SMEM_BYTES (NSTAGE * STAGE_W * 4)

__device__ __forceinline__ void cp16(uint32_t s, const void* g) {
    asm volatile("cp.async.cg.shared.global [%0], [%1], 16;" :: "r"(s), "l"(g));
}

__device__ __forceinline__ void mma_bf16(float* c, const uint32_t* a, const uint32_t* b) {
    asm volatile(
        "mma.sync.aligned.m16n8k16.row.col.f32.bf16.bf16.f32 "
        "{%0,%1,%2,%3}, {%4,%5,%6,%7}, {%8,%9}, {%0,%1,%2,%3};"
        : "+f"(c[0]), "+f"(c[1]), "+f"(c[2]), "+f"(c[3])
        : "r"(a[0]), "r"(a[1]), "r"(a[2]), "r"(a[3]), "r"(b[0]), "r"(b[1]));
}

// EPI: 0 = bias, 1 = bias + resid, 2 = bias + gelu
template <int EPI>
__global__ void __launch_bounds__(256, 1)
gemm_bf_kernel(const __nv_bfloat16* __restrict__ A2, const __nv_bfloat16* __restrict__ W2T,
               const float* __restrict__ bias, const float* __restrict__ resid,
               float* __restrict__ C, int M, int N, int K2) {
    extern __shared__ uint32_t smw[];
    const uint32_t smem_base = (uint32_t)__cvta_generic_to_shared(smw);

    const int tid = threadIdx.x;
    const int wid = tid >> 5;
    const int lane = tid & 31;
    const int g = lane >> 2;
    const int t = lane & 3;
    const int m0 = blockIdx.y * BM;
    const int n0 = blockIdx.x * BN;
    const int wm = (wid & 1) * 64;
    const int wn = (wid >> 1) * 64;

    const int nch = K2 >> 6;   // chunks of 64 halves

    auto load_chunk = [&](int s, int c) {
        int k0 = c * 64;                              // in bf16 halves
        uint32_t sb = smem_base + (uint32_t)(s * STAGE_W) * 4u;
        // A: 128 rows x 8 segs(16B) = 1024, 4/thread
#pragma unroll
        for (int i = 0; i < 4; i++) {
            int idx = tid + i * 256;
            int ar = idx >> 3, sg = idx & 7;
            cp16(sb + (uint32_t)(ar * ASTW + sg * 4) * 4u,
                 (const char*)A2 + ((size_t)(m0 + ar) * K2 + k0 + sg * 8) * 2);
        }
        // B: 256 rows x 8 segs = 2048, 8/thread
        uint32_t sbB = sb + (uint32_t)A_TILE_W * 4u;
#pragma unroll
        for (int i = 0; i < 8; i++) {
            int idx = tid + i * 256;
            int br = idx >> 3, sg = idx & 7;
            cp16(sbB + (uint32_t)(br * BSTW + sg * 4) * 4u,
                 (const char*)W2T + ((size_t)(n0 + br) * K2 + k0 + sg * 8) * 2);
        }
        asm volatile("cp.async.commit_group;");
    };

    float acc[4][8][4];
#pragma unroll
    for (int i = 0; i < 4; i++)
#pragma unroll
        for (int j = 0; j < 8; j++)
#pragma unroll
            for (int r = 0; r < 4; r++) acc[i][j][r] = 0.f;

    load_chunk(0, 0);
    load_chunk(1, 1);

    for (int c = 0; c < nch; c++) {
        asm volatile("cp.async.wait_group 1;");
        __syncthreads();
        if (c + 2 < nch) load_chunk((c + 2) % NSTAGE, c + 2);
        else asm volatile("cp.async.commit_group;");

        const uint32_t* As_ = smw + (c % NSTAGE) * STAGE_W;
        const uint32_t* Bs_ = As_ + A_TILE_W;
#pragma unroll
        for (int ks = 0; ks < 4; ks++) {           // 4 x k16 per chunk
            int kw = ks * 8;
            uint32_t a[4][4];
#pragma unroll
            for (int mt = 0; mt < 4; mt++) {
                int r = wm + mt * 16 + g;
                a[mt][0] = As_[r * ASTW + kw + t];
                a[mt][1] = As_[(r + 8) * ASTW + kw + t];
                a[mt][2] = As_[r * ASTW + kw + t + 4];
                a[mt][3] = As_[(r + 8) * ASTW + kw + t + 4];
            }
            uint32_t b[8][2];
#pragma unroll
            for (int nt = 0; nt < 8; nt++) {
                int cc = wn + nt * 8 + g;
                b[nt][0] = Bs_[cc * BSTW + kw + t];
                b[nt][1] = Bs_[cc * BSTW + kw + t + 4];
            }
#pragma unroll
            for (int mt = 0; mt < 4; mt++)
#pragma unroll
                for (int nt = 0; nt < 8; nt++)
                    mma_bf16(acc[mt][nt], a[mt], b[nt]);
        }
        __syncthreads();
    }

    // epilogue: c-layout (g,2t),(g,2t+1),(g+8,2t),(g+8,2t+1)
#pragma unroll
    for (int mt = 0; mt < 4; mt++) {
#pragma unroll
        for (int nt = 0; nt < 8; nt++) {
            int r0 = m0 + wm + mt * 16 + g;
            int c0 = n0 + wn + nt * 8 + 2 * t;
#pragma unroll
            for (int half = 0; half < 2; half++) {
                int r = r0 + half * 8;
#pragma unroll
                for (int e = 0; e < 2; e++) {
                    int cc = c0 + e;
                    float v = acc[mt][nt][half * 2 + e] + bias[cc];
                    if (EPI == 1) v += resid[(size_t)r * N + cc];
                    if (EPI == 2) {
                        float x = v;
                        float th = tanhf(0.7978845608028654f *
                                         (x + 0.044715f * x * x * x));
                        v = 0.5f * x * (1.f + th);
                    }
                    C[(size_t)r * N + cc] = v;
                }
            }
        }
    }
}

// ---------------- RoPE (in-place on q,k of g_qkv) ---------------------------
__global__ void rope_kernel(float* __restrict__ qkv, const float* __restrict__ coords,
                            const float* __restrict__ inv_freq) {
    int n = blockIdx.x;
    __shared__ alignas(16) float cs[32];
    __shared__ alignas(16) float sn[32];
    int t = threadIdx.x;
    if (t < 32) {
        int d = t >> 3, f = t & 7;
        float ang = coords[n * 4 + d] * inv_freq[d * 8 + f];
        cs[t] = cosf(ang);
        sn[t] = sinf(ang);
    }
    __syncthreads();
#pragma unroll
    for (int w = t; w < 1024; w += 256) {
        int qk = w >> 9;
        int h = (w >> 5) & 15;
        int p = w & 31;
        float* base = qkv + (size_t)n * QKV3 + qk * EMBED + h * HDIM;
        float x1 = base[p], x2 = base[p + 32];
        base[p]      = x1 * cs[p] - x2 * sn[p];
        base[p + 32] = x2 * cs[p] + x1 * sn[p];
    }
}

// ---------------- FlashAttention with tf32 mma (R12, unchanged) -------------
__device__ __forceinline__ void mma_tf32(float* c, const uint32_t* a, const uint32_t* b) {
    asm volatile(
        "mma.sync.aligned.m16n8k8.row.col.f32.tf32.tf32.f32 "
        "{%0,%1,%2,%3}, {%4,%5,%6,%7}, {%8,%9}, {%0,%1,%2,%3};"
        : "+f"(c[0]), "+f"(c[1]), "+f"(c[2]), "+f"(c[3])
        : "r"(a[0]), "r"(a[1]), "r"(a[2]), "r"(a[3]), "r"(b[0]), "r"(b[1]));
}

#define KS_STRIDE 76
#define VS_STRIDE 72
#define PS_STRIDE 68
#define ATTN_SMEM_FLOATS (64 * KS_STRIDE + 64 * VS_STRIDE + 64 * PS_STRIDE)
#define ATTN_SMEM_BYTES (ATTN_SMEM_FLOATS * 4)

__global__ void __launch_bounds__(128, 1)
attn_mma_kernel(const float* __restrict__ qkv, const int* __restrict__ cu,
                float* __restrict__ out) {
    extern __shared__ float asmem[];
    float* Ks = asmem;
    float* Vs = Ks + 64 * KS_STRIDE;
    float* Ps = Vs + 64 * VS_STRIDE;
    __shared__ int kst[64], ken[64];

    const int h = blockIdx.y;
    const int qb = blockIdx.x * 64;
    const int tid = threadIdx.x;
    const int wid = tid >> 5;
    const int lane = tid & 31;
    const int g = lane >> 2;
    const int t = lane & 3;
    const int r0 = wid * 16 + g;
    const int r1 = r0 + 8;

    if (tid < 64) {
        int qi = qb + tid;
        int s = 0;
#pragma unroll
        for (int i = 1; i <= 7; i++)
            if (cu[i] <= qi) s = i;
        kst[tid] = cu[s];
        ken[tid] = cu[s + 1];
    }
    __syncthreads();
    const int kb0 = kst[0] & ~63;
    const int keM = ken[63];
    const int ks0 = kst[r0], ke0 = ken[r0];
    const int ks1 = kst[r1], ke1 = ken[r1];

    uint32_t qf[8][4];
    {
        const float* q0 = qkv + (size_t)(qb + r0) * QKV3 + h * HDIM;
        const float* q1 = qkv + (size_t)(qb + r1) * QKV3 + h * HDIM;
#pragma unroll
        for (int ks = 0; ks < 8; ks++) {
            qf[ks][0] = __float_as_uint(q0[ks * 8 + t] * 0.125f);
            qf[ks][1] = __float_as_uint(q1[ks * 8 + t] * 0.125f);
            qf[ks][2] = __float_as_uint(q0[ks * 8 + t + 4] * 0.125f);
            qf[ks][3] = __float_as_uint(q1[ks * 8 + t + 4] * 0.125f);
        }
    }

    float O[8][4];
#pragma unroll
    for (int nt = 0; nt < 8; nt++)
#pragma unroll
        for (int e = 0; e < 4; e++) O[nt][e] = 0.f;
    float m0 = -1e30f, m1 = -1e30f, l0 = 0.f, l1 = 0.f;

    for (int kt = kb0; kt < keM; kt += 64) {
        __syncthreads();
        {
            int row = tid >> 1, cb = (tid & 1) * 32;
            const float* kp = qkv + (size_t)(kt + row) * QKV3 + EMBED + h * HDIM + cb;
            const float* vp = qkv + (size_t)(kt + row) * QKV3 + 2 * EMBED + h * HDIM + cb;
            float4* kd = (float4*)&Ks[row * KS_STRIDE + cb];
            float4* vd = (float4*)&Vs[row * VS_STRIDE + cb];
#pragma unroll
            for (int d4 = 0; d4 < 8; d4++) {
                kd[d4] = ((const float4*)kp)[d4];
                vd[d4] = ((const float4*)vp)[d4];
            }
        }
        __syncthreads();

        float S[8][4];
#pragma unroll
        for (int nt = 0; nt < 8; nt++)
#pragma unroll
            for (int e = 0; e < 4; e++) S[nt][e] = 0.f;
#pragma unroll
        for (int ks = 0; ks < 8; ks++) {
#pragma unroll
            for (int nt = 0; nt < 8; nt++) {
                uint32_t b[2];
                b[0] = __float_as_uint(Ks[(nt * 8 + g) * KS_STRIDE + ks * 8 + t]);
                b[1] = __float_as_uint(Ks[(nt * 8 + g) * KS_STRIDE + ks * 8 + t + 4]);
                mma_tf32(S[nt], qf[ks], b);
            }
        }

        float cm0 = -1e30f, cm1 = -1e30f;
#pragma unroll
        for (int nt = 0; nt < 8; nt++) {
            int c0 = kt + nt * 8 + 2 * t;
            int c1 = c0 + 1;
            S[nt][0] = (c0 >= ks0 && c0 < ke0) ? S[nt][0] : -1e30f;
            S[nt][1] = (c1 >= ks0 && c1 < ke0) ? S[nt][1] : -1e30f;
            S[nt][2] = (c0 >= ks1 && c0 < ke1) ? S[nt][2] : -1e30f;
            S[nt][3] = (c1 >= ks1 && c1 < ke1) ? S[nt][3] : -1e30f;
            cm0 = fmaxf(cm0, fmaxf(S[nt][0], S[nt][1]));
            cm1 = fmaxf(cm1, fmaxf(S[nt][2], S[nt][3]));
        }
        cm0 = fmaxf(cm0, __shfl_xor_sync(0xffffffffu, cm0, 1));
        cm0 = fmaxf(cm0, __shfl_xor_sync(0xffffffffu, cm0, 2));
        cm1 = fmaxf(cm1, __shfl_xor_sync(0xffffffffu, cm1, 1));
        cm1 = fmaxf(cm1, __shfl_xor_sync(0xffffffffu, cm1, 2));
        float mn0 = fmaxf(m0, cm0);
        float mn1 = fmaxf(m1, cm1);
        float sc0 = __expf(m0 - mn0);
        float sc1 = __expf(m1 - mn1);

        float ps0 = 0.f, ps1 = 0.f;
#pragma unroll
        for (int nt = 0; nt < 8; nt++) {
            float p00 = (S[nt][0] > -1e29f) ? __expf(S[nt][0] - mn0) : 0.f;
            float p01 = (S[nt][1] > -1e29f) ? __expf(S[nt][1] - mn0) : 0.f;
            float p10 = (S[nt][2] > -1e29f) ? __expf(S[nt][2] - mn1) : 0.f;
            float p11 = (S[nt][3] > -1e29f) ? __expf(S[nt][3] - mn1) : 0.f;
            ps0 += p00 + p01;
            ps1 += p10 + p11;
            Ps[r0 * PS_STRIDE + nt * 8 + 2 * t]     = p00;
            Ps[r0 * PS_STRIDE + nt * 8 + 2 * t + 1] = p01;
            Ps[r1 * PS_STRIDE + nt * 8 + 2 * t]     = p10;
            Ps[r1 * PS_STRIDE + nt * 8 + 2 * t + 1] = p11;
            O[nt][0] *= sc0; O[nt][1] *= sc0;
            O[nt][2] *= sc1; O[nt][3] *= sc1;
        }
        ps0 += __shfl_xor_sync(0xffffffffu, ps0, 1);
        ps0 += __shfl_xor_sync(0xffffffffu, ps0, 2);
        ps1 += __shfl_xor_sync(0xffffffffu, ps1, 1);
        ps1 += __shfl_xor_sync(0xffffffffu, ps1, 2);
        l0 = l0 * sc0 + ps0;
        l1 = l1 * sc1 + ps1;
        m0 = mn0; m1 = mn1;
        __syncwarp();

#pragma unroll
        for (int ks2 = 0; ks2 < 8; ks2++) {
            uint32_t pa[4];
            pa[0] = __float_as_uint(Ps[r0 * PS_STRIDE + ks2 * 8 + t]);
            pa[1] = __float_as_uint(Ps[r1 * PS_STRIDE + ks2 * 8 + t]);
            pa[2] = __float_as_uint(Ps[r0 * PS_STRIDE + ks2 * 8 + t + 4]);
            pa[3] = __float_as_uint(Ps[r1 * PS_STRIDE + ks2 * 8 + t + 4]);
#pragma unroll
            for (int nt = 0; nt < 8; nt++) {
                uint32_t vb[2];
                vb[0] = __float_as_uint(Vs[(ks2 * 8 + t) * VS_STRIDE + nt * 8 + g]);
                vb[1] = __float_as_uint(Vs[(ks2 * 8 + t + 4) * VS_STRIDE + nt * 8 + g]);
                mma_tf32(O[nt], pa, vb);
            }
        }
        __syncwarp();
    }

    float il0 = 1.f / l0, il1 = 1.f / l1;
    float* o0 = out + (size_t)(qb + r0) * EMBED + h * HDIM;
    float* o1 = out + (size_t)(qb + r1) * EMBED + h * HDIM;
#pragma unroll
    for (int nt = 0; nt < 8; nt++) {
        o0[nt * 8 + 2 * t]     = O[nt][0] * il0;
        o0[nt * 8 + 2 * t + 1] = O[nt][1] * il0;
        o1[nt * 8 + 2 * t]     = O[nt][2] * il1;
        o1[nt * 8 + 2 * t + 1] = O[nt][3] * il1;
    }
}

// ---------------- LayerNorm -------------------------------------------------
__device__ __forceinline__ float blockReduceSum(float v) {
    __shared__ alignas(16) float red[8];
    int lane = threadIdx.x & 31, wid = threadIdx.x >> 5;
#pragma unroll
    for (int off = 16; off; off >>= 1) v += __shfl_xor_sync(0xffffffffu, v, off);
    __syncthreads();
    if (lane == 0) red[wid] = v;
    __syncthreads();
    v = (threadIdx.x < 8) ? red[threadIdx.x] : 0.f;
    if (wid == 0) {
#pragma unroll
        for (int off = 4; off; off >>= 1) v += __shfl_xor_sync(0xffu, v, off);
        if (lane == 0) red[0] = v;
    }
    __syncthreads();
    return red[0];
}

__global__ void __launch_bounds__(256)
layernorm_kernel(const float* __restrict__ x, const float* __restrict__ g,
                 const float* __restrict__ b, float* __restrict__ y) {
    int row = blockIdx.x;
    int t = threadIdx.x;
    const float4* xr = (const float4*)(x + (size_t)row * EMBED);
    float4 v = xr[t];
    float s = (v.x + v.y) + (v.z + v.w);
    float mean = blockReduceSum(s) * (1.f / 1024.f);
    float dx = v.x - mean, dy = v.y - mean, dz = v.z - mean, dw = v.w - mean;
    float sq = dx * dx + dy * dy + dz * dz + dw * dw;
    float var = blockReduceSum(sq) * (1.f / 1024.f);
    float rstd = rsqrtf(var + 1e-5f);
    int c = t * 4;
    float g0 = g[c], g1 = g[c + 1], g2 = g[c + 2], g3 = g[c + 3];
    float b0 = b[c], b1 = b[c + 1], b2 = b[c + 2], b3 = b[c + 3];
    float* yr = y + (size_t)row * EMBED + c;
    yr[0] = dx * rstd * g0 + b0;
    yr[1] = dy * rstd * g1 + b1;
    yr[2] = dz * rstd * g2 + b2;
    yr[3] = dw * rstd * g3 + b3;
}

// ---------------- launch ----------------------------------------------------
extern "C" void kernel_launch(void* const* d_in, const int* in_sizes, int n_in,
                              void* d_out, int out_size) {
    const float* coords   = (const float*)d_in[0];
    const float* feats    = (const float*)d_in[1];
    const int*   cu       = (const int*)d_in[2];
    const float* Wqkv     = (const float*)d_in[3];
    const float* bqkv     = (const float*)d_in[4];
    const float* Wo       = (const float*)d_in[5];
    const float* bo       = (const float*)d_in[6];
    const float* inv_freq = (const float*)d_in[7];
    const float* ln1_g    = (const float*)d_in[8];
    const float* ln1_b    = (const float*)d_in[9];
    const float* W1       = (const float*)d_in[10];
    const float* b1       = (const float*)d_in[11];
    const float* W2       = (const float*)d_in[12];
    const float* b2       = (const float*)d_in[13];
    const float* ln2_g    = (const float*)d_in[14];
    const float* ln2_b    = (const float*)d_in[15];
    float* out = (float*)d_out;

    float *qkv, *attn, *res1, *h, *ffn;
    __nv_bfloat16 *featsS, *attnS, *hS, *ffnS, *wqkvT, *woT, *w1T, *w2T;
    cudaGetSymbolAddress((void**)&qkv, g_qkv);
    cudaGetSymbolAddress((void**)&attn, g_attn);
    cudaGetSymbolAddress((void**)&res1, g_res1);
    cudaGetSymbolAddress((void**)&h, g_h);
    cudaGetSymbolAddress((void**)&ffn, g_ffn);
    cudaGetSymbolAddress((void**)&featsS, g_featsS);
    cudaGetSymbolAddress((void**)&attnS, g_attnS);
    cudaGetSymbolAddress((void**)&hS, g_hS);
    cudaGetSymbolAddress((void**)&ffnS, g_ffnS);
    cudaGetSymbolAddress((void**)&wqkvT, g_wqkvT);
    cudaGetSymbolAddress((void**)&woT, g_woT);
    cudaGetSymbolAddress((void**)&w1T, g_w1T);
    cudaGetSymbolAddress((void**)&w2T, g_w2T);

    cudaFuncSetAttribute(gemm_bf_kernel<0>,
                         cudaFuncAttributeMaxDynamicSharedMemorySize, GEMM_SMEM_BYTES);
    cudaFuncSetAttribute(gemm_bf_kernel<1>,
                         cudaFuncAttributeMaxDynamicSharedMemorySize, GEMM_SMEM_BYTES);
    cudaFuncSetAttribute(gemm_bf_kernel<2>,
                         cudaFuncAttributeMaxDynamicSharedMemorySize, GEMM_SMEM_BYTES);
    cudaFuncSetAttribute(attn_mma_kernel,
                         cudaFuncAttributeMaxDynamicSharedMemorySize, ATTN_SMEM_BYTES);

    // 0. preprocess: 4 weight transpose-splits + feats split (launches 0-4)
    transpose_split_kernel<<<dim3(QKV3 / 32, EMBED / 32), 256>>>(Wqkv, wqkvT, EMBED, QKV3);
    transpose_split_kernel<<<dim3(EMBED / 32, EMBED / 32), 256>>>(Wo, woT, EMBED, EMBED);
    transpose_split_kernel<<<dim3(FFN / 32, EMBED / 32), 256>>>(W1, w1T, EMBED, FFN);
    transpose_split_kernel<<<dim3(EMBED / 32, FFN / 32), 256>>>(W2, w2T, FFN, EMBED);
    split_kernel<10><<<(N_TOK * EMBED) / 256, 256>>>(feats, featsS, N_TOK * EMBED);

    // 1. QKV projection (launch 5 -> ncu capture)
    gemm_bf_kernel<0><<<dim3(QKV3 / BN, N_TOK / BM), 256, GEMM_SMEM_BYTES>>>(
        featsS, wqkvT, bqkv, nullptr, qkv, N_TOK, QKV3, 3 * EMBED);
    // 2. RoPE
    rope_kernel<<<N_TOK, 256>>>(qkv, coords, inv_freq);
    // 3. FlashAttention (tf32 mma)
    attn_mma_kernel<<<dim3(N_TOK / 64, NHEAD), 128, ATTN_SMEM_BYTES>>>(qkv, cu, attn);
    // 4. split attn; Wo projection + residual(feats)
    split_kernel<10><<<(N_TOK * EMBED) / 256, 256>>>(attn, attnS, N_TOK * EMBED);
    gemm_bf_kernel<1><<<dim3(EMBED / BN, N_TOK / BM), 256, GEMM_SMEM_BYTES>>>(
        attnS, woT, bo, feats, res1, N_TOK, EMBED, 3 * EMBED);
    // 5. LN1 -> h; split h
    layernorm_kernel<<<N_TOK, 256>>>(res1, ln1_g, ln1_b, h);
    split_kernel<10><<<(N_TOK * EMBED) / 256, 256>>>(h, hS, N_TOK * EMBED);
    // 6. FFN up + gelu
    gemm_bf_kernel<2><<<dim3(FFN / BN, N_TOK / BM), 256, GEMM_SMEM_BYTES>>>(
        hS, w1T, b1, nullptr, ffn, N_TOK, FFN, 3 * EMBED);
    // 7. split ffn; FFN down + residual(h)
    split_kernel<12><<<(N_TOK * FFN) / 256, 256>>>(ffn, ffnS, N_TOK * FFN);
    gemm_bf_kernel<1><<<dim3(EMBED / BN, N_TOK / BM), 256, GEMM_SMEM_BYTES>>>(
        ffnS, w2T, b2, h, res1, N_TOK, EMBED, 3 * FFN);
    // 8. LN2 -> out
    layernorm_kernel<<<N_TOK, 256>>>(res1, ln2_g, ln2_b, out);
}